// round 13
// baseline (speedup 1.0000x reference)
#include <cuda_runtime.h>
#include <cuda_bf16.h>
#include <cstdint>

#define BB 4
#define LEN 512
#define LEN1 512
#define DIM_IN 512
#define DIM_H 512
#define DIM_M 256
#define DIM_V 512

#define LDK 20   // smem k-stride (16 k + 4 pad) words
#define LDN 72   // smem n-stride (64 n + 8 pad) words

#define L2E 1.4426950408889634f

// Scratch
__device__ __align__(16) float    g_kx[BB * LEN * DIM_M];   // [b][l][m]
__device__ __align__(16) float    g_qh[BB * LEN1 * DIM_M];  // [b][q][m]
__device__ __align__(16) float    g_sc[BB * LEN1 * LEN];    // [b][q][l]: exp(s) as tf32 bits
__device__ __align__(16) unsigned g_vt[BB * LEN * DIM_V];   // values as tf32 bits
__device__ __align__(16) float    g_part[BB * LEN1 * 16];   // per (row, l-tile): S_tile

__device__ __forceinline__ float tanh_fast(float x) {
    float y;
    asm("tanh.approx.f32 %0, %1;" : "=f"(y) : "f"(x));
    return y;
}
__device__ __forceinline__ unsigned f2tf(float x) {
    unsigned u;
    asm("cvt.rna.tf32.f32 %0, %1;" : "=r"(u) : "f"(x));
    return u;
}
__device__ __forceinline__ void mma_tf32(float* d, const unsigned* a, const unsigned* b) {
    asm volatile(
        "mma.sync.aligned.m16n8k8.row.col.f32.tf32.tf32.f32 "
        "{%0,%1,%2,%3}, {%4,%5,%6,%7}, {%8,%9}, {%0,%1,%2,%3};"
        : "+f"(d[0]), "+f"(d[1]), "+f"(d[2]), "+f"(d[3])
        : "r"(a[0]), "r"(a[1]), "r"(a[2]), "r"(a[3]), "r"(b[0]), "r"(b[1]));
}
__device__ __forceinline__ void cp16(uint32_t smem_dst, const void* gmem_src) {
    asm volatile("cp.async.cg.shared.global [%0], [%1], 16;"
                 :: "r"(smem_dst), "l"(gmem_src));
}
#define CP_COMMIT() asm volatile("cp.async.commit_group;")
#define CP_WAIT2()  asm volatile("cp.async.wait_group 2;" ::: "memory")

// PDL primitives
#define GDC_LAUNCH_DEPENDENTS() asm volatile("griddepcontrol.launch_dependents;")
#define GDC_WAIT()              asm volatile("griddepcontrol.wait;" ::: "memory")

// ---------------------------------------------------------------------------
// proj (NT, tf32 mma, 4-stage cp.async), per batch b. Block 64x64, 8 warps.
// z=0: keys[b]@Wx -> g_kx[b] ; z=1: query[b]@Wh + bh -> g_qh[b] ;
// z=2: rider blocks convert values[b] (fp32) -> g_vt[b] (tf32 bits).
// Fires launch_dependents at entry (score's pre-wait code touches only w).
// ---------------------------------------------------------------------------
__global__ __launch_bounds__(256) void proj_tc(
    const float* __restrict__ keys, const float* __restrict__ query,
    const float* __restrict__ Wx, const float* __restrict__ Wh,
    const float* __restrict__ bh, const float* __restrict__ values, int b)
{
    GDC_LAUNCH_DEPENDENTS();

    int tid = threadIdx.x;

    if (blockIdx.z == 2) {
        size_t base = (size_t)b * LEN * DIM_V / 4;
        const float4* src = (const float4*)values + base;
        uint4* dst = (uint4*)g_vt + base;
        int blk = blockIdx.y * 4 + blockIdx.x;        // 0..31
        int t   = blk * 256 + tid;                    // 0..8191
        #pragma unroll
        for (int i = 0; i < 8; i++) {
            int idx = t + i * 8192;
            float4 v = src[idx];
            uint4 u;
            u.x = f2tf(v.x); u.y = f2tf(v.y); u.z = f2tf(v.z); u.w = f2tf(v.w);
            dst[idx] = u;
        }
        return;
    }

    const float* A; const float* W; float* C; const float* bias;
    if (blockIdx.z == 0) {
        A = keys  + (size_t)b * LEN * DIM_IN;  W = Wx;
        C = g_kx  + (size_t)b * LEN * DIM_M;   bias = nullptr;
    } else {
        A = query + (size_t)b * LEN1 * DIM_H;  W = Wh;
        C = g_qh  + (size_t)b * LEN1 * DIM_M;  bias = bh;
    }

    __shared__ __align__(16) float As[4][64 * LDK];
    __shared__ __align__(16) float Ws[4][64 * LDK];

    int lane = tid & 31;
    int wid  = tid >> 5;
    int warp_m = (wid & 1) * 32;
    int warp_n = (wid >> 1) * 16;
    int gid = lane >> 2;
    int tig = lane & 3;

    int rb = blockIdx.y * 64;
    int nb = blockIdx.x * 64;

    int crow = tid >> 2;
    int cku  = (tid & 3) * 4;
    const float* Agp = A + (size_t)(rb + crow) * 512 + cku;
    const float* Wgp = W + (size_t)(nb + crow) * 512 + cku;
    uint32_t sA = (uint32_t)__cvta_generic_to_shared(&As[0][0]) + (crow * LDK + cku) * 4;
    uint32_t sW = (uint32_t)__cvta_generic_to_shared(&Ws[0][0]) + (crow * LDK + cku) * 4;
    const uint32_t stageB = 64 * LDK * 4;

    float acc[2][2][4] = {};

    #pragma unroll
    for (int s = 0; s < 3; s++) {
        cp16(sA + s * stageB, Agp + s * 16);
        cp16(sW + s * stageB, Wgp + s * 16);
        CP_COMMIT();
    }

    for (int i = 0; i < 32; i++) {
        CP_WAIT2();
        __syncthreads();
        int ls = i + 3;
        if (ls < 32) {
            uint32_t off = (uint32_t)(ls & 3) * stageB;
            cp16(sA + off, Agp + ls * 16);
            cp16(sW + off, Wgp + ls * 16);
        }
        CP_COMMIT();

        const float* Ab = &As[i & 3][0];
        const float* Wb = &Ws[i & 3][0];
        #pragma unroll
        for (int ks = 0; ks < 16; ks += 8) {
            unsigned af[2][4], bf[2][2];
            #pragma unroll
            for (int mm = 0; mm < 2; mm++) {
                const float* p = &Ab[(warp_m + mm * 16 + gid) * LDK + ks + tig];
                af[mm][0] = f2tf(p[0]);
                af[mm][1] = f2tf(p[8 * LDK]);
                af[mm][2] = f2tf(p[4]);
                af[mm][3] = f2tf(p[8 * LDK + 4]);
            }
            #pragma unroll
            for (int nn = 0; nn < 2; nn++) {
                const float* p = &Wb[(warp_n + nn * 8 + gid) * LDK + ks + tig];
                bf[nn][0] = f2tf(p[0]);
                bf[nn][1] = f2tf(p[4]);
            }
            #pragma unroll
            for (int mm = 0; mm < 2; mm++)
                #pragma unroll
                for (int nn = 0; nn < 2; nn++)
                    mma_tf32(acc[mm][nn], af[mm], bf[nn]);
        }
    }

    #pragma unroll
    for (int mm = 0; mm < 2; mm++) {
        int r0 = rb + warp_m + mm * 16 + gid;
        #pragma unroll
        for (int nn = 0; nn < 2; nn++) {
            int c = nb + warp_n + nn * 8 + 2 * tig;
            float2 v0 = make_float2(acc[mm][nn][0], acc[mm][nn][1]);
            float2 v1 = make_float2(acc[mm][nn][2], acc[mm][nn][3]);
            if (bias) {
                float2 bb = *(const float2*)&bias[c];
                v0.x += bb.x; v0.y += bb.y;
                v1.x += bb.x; v1.y += bb.y;
            }
            *(float2*)&C[(size_t)r0 * DIM_M + c]       = v0;
            *(float2*)&C[(size_t)(r0 + 8) * DIM_M + c] = v1;
        }
    }
}

// ---------------------------------------------------------------------------
// Scores, per batch b. s = sum_m w[m]*tanh(kx+qh) (fp32 MUFU tanh).
// No max subtraction (|s| <= ~8). Stores e = exp2(s*L2E) as tf32 bits and
// per-(row, 32-l-tile) partial sum S_tile in g_part.
// PDL: pre-wait loads w_s + addr math; waits for proj; then fires
// launch_dependents so av can prefetch V (g_vt complete at that point).
// ---------------------------------------------------------------------------
__global__ __launch_bounds__(256) void score_kernel(const float* __restrict__ w, int b)
{
    __shared__ float kxs[128][34];
    __shared__ float qhs[128][34];
    __shared__ float w_s[DIM_M];

    int tid = threadIdx.x;
    int tx = tid & 15, ty = tid >> 4;
    int lb = blockIdx.x * 32;
    int qb = blockIdx.y * 32;

    w_s[tid] = w[tid];                       // input, safe pre-wait

    const float* kxp = g_kx + (size_t)(b * LEN  + lb) * DIM_M;
    const float* qhp = g_qh + (size_t)(b * LEN1 + qb) * DIM_M;

    int mloc  = tid & 127;
    int lhalf = tid >> 7;

    GDC_WAIT();                              // proj outputs now visible
    GDC_LAUNCH_DEPENDENTS();                 // av may launch + prefetch g_vt

    float acc00 = 0.f, acc01 = 0.f, acc10 = 0.f, acc11 = 0.f;

    for (int h = 0; h < 2; h++) {
        __syncthreads();
        int mg = h * 128 + mloc;
        #pragma unroll
        for (int i = 0; i < 16; i++) {
            int row = lhalf * 16 + i;
            kxs[mloc][row] = kxp[row * DIM_M + mg];
            qhs[mloc][row] = qhp[row * DIM_M + mg];
        }
        __syncthreads();

        #pragma unroll 8
        for (int mm = 0; mm < 128; mm++) {
            float  wm = w_s[h * 128 + mm];
            float2 qa = *(const float2*)&qhs[mm][ty * 2];
            float2 kb = *(const float2*)&kxs[mm][tx * 2];
            acc00 += wm * tanh_fast(qa.x + kb.x);
            acc01 += wm * tanh_fast(qa.x + kb.y);
            acc10 += wm * tanh_fast(qa.y + kb.x);
            acc11 += wm * tanh_fast(qa.y + kb.y);
        }
    }

    float e00 = exp2f(acc00 * L2E);
    float e01 = exp2f(acc01 * L2E);
    float e10 = exp2f(acc10 * L2E);
    float e11 = exp2f(acc11 * L2E);

    float S0 = e00 + e01;
    float S1 = e10 + e11;
    #pragma unroll
    for (int s = 1; s < 16; s <<= 1) {
        S0 += __shfl_xor_sync(0xFFFFFFFFu, S0, s);
        S1 += __shfl_xor_sync(0xFFFFFFFFu, S1, s);
    }

    float* o = g_sc + (size_t)(b * LEN1 + qb + ty * 2) * LEN + lb + tx * 2;
    o[0]       = __uint_as_float(f2tf(e00));
    o[1]       = __uint_as_float(f2tf(e01));
    o[LEN]     = __uint_as_float(f2tf(e10));
    o[LEN + 1] = __uint_as_float(f2tf(e11));

    if (tx == 0) {
        int q0 = qb + ty * 2;
        float* pp = g_part + (size_t)(b * LEN1 + q0) * 16 + blockIdx.x;
        pp[0]  = S0;
        pp[16] = S1;
    }
}

// ---------------------------------------------------------------------------
// av (NN, tf32 mma, 4-stage cp.async), per batch b. Block 64x64, 8 warps.
// PDL: launches during score; prefetches V stages 0..2 pre-wait (V depends
// only on proj), then waits for score, then issues E stages. Commit-group
// order: V0,V1,V2,E0,E1,E2, then one (E+V) group per mainloop iter — stage i
// ready iff group 3+i complete, so the mainloop's wait_group 2 is unchanged.
// Normalization (1/S_row) applied in the epilogue.
// ---------------------------------------------------------------------------
__global__ __launch_bounds__(256) void av_tc(float* __restrict__ out, int b)
{
    const unsigned* E = (const unsigned*)g_sc + (size_t)b * LEN1 * LEN;
    const unsigned* V = g_vt + (size_t)b * LEN * DIM_V;
    float*          C = out  + (size_t)b * LEN1 * DIM_V;

    __shared__ __align__(16) unsigned Es[4][64 * LDK];
    __shared__ __align__(16) unsigned Vs[4][16 * LDN];
    __shared__ float sinv[64];

    int tid  = threadIdx.x;
    int lane = tid & 31;
    int wid  = tid >> 5;
    int warp_m = (wid & 1) * 32;
    int warp_n = (wid >> 1) * 16;
    int gid = lane >> 2;
    int tig = lane & 3;

    int rb = blockIdx.y * 64;
    int nb = blockIdx.x * 64;

    int erow = tid >> 2;
    int eku  = (tid & 3) * 4;
    int vrow = tid >> 4;
    int vu   = (tid & 15) * 4;
    const unsigned* Egp = E + (size_t)(rb + erow) * LEN + eku;
    const unsigned* Vgp = V + (size_t)vrow * DIM_V + nb + vu;
    uint32_t sE = (uint32_t)__cvta_generic_to_shared(&Es[0][0]) + (erow * LDK + eku) * 4;
    uint32_t sV = (uint32_t)__cvta_generic_to_shared(&Vs[0][0]) + (vrow * LDN + vu) * 4;
    const uint32_t stageE = 64 * LDK * 4;
    const uint32_t stageV = 16 * LDN * 4;

    // Pre-wait: prefetch V stages (g_vt written by proj, complete before
    // score fired launch_dependents). Groups 0..2.
    #pragma unroll
    for (int s = 0; s < 3; s++) {
        cp16(sV + s * stageV, Vgp + (size_t)s * 16 * DIM_V);
        CP_COMMIT();
    }

    GDC_WAIT();   // score outputs (g_sc, g_part) now visible

    // Post-wait: E stages. Groups 3..5.
    #pragma unroll
    for (int s = 0; s < 3; s++) {
        cp16(sE + s * stageE, Egp + s * 16);
        CP_COMMIT();
    }

    float acc[2][2][4] = {};

    // Prologue: per-row inverse sums (threads 0..63, one row each).
    if (tid < 64) {
        const float4* pp = (const float4*)&g_part[(size_t)(b * LEN1 + rb + tid) * 16];
        float4 p0 = pp[0], p1 = pp[1], p2 = pp[2], p3 = pp[3];
        float S = ((p0.x + p0.y) + (p0.z + p0.w))
                + ((p1.x + p1.y) + (p1.z + p1.w))
                + ((p2.x + p2.y) + (p2.z + p2.w))
                + ((p3.x + p3.y) + (p3.z + p3.w));
        sinv[tid] = 1.0f / S;
    }
    __syncthreads();

    for (int i = 0; i < 32; i++) {
        CP_WAIT2();
        __syncthreads();
        int ls = i + 3;
        if (ls < 32) {
            uint32_t offE = (uint32_t)(ls & 3) * stageE;
            uint32_t offV = (uint32_t)(ls & 3) * stageV;
            cp16(sE + offE, Egp + ls * 16);
            cp16(sV + offV, Vgp + (size_t)ls * 16 * DIM_V);
        }
        CP_COMMIT();

        const unsigned* Eb = &Es[i & 3][0];
        const unsigned* Vb = &Vs[i & 3][0];
        #pragma unroll
        for (int ks = 0; ks < 16; ks += 8) {
            unsigned af[2][4], bf[2][2];
            #pragma unroll
            for (int mm = 0; mm < 2; mm++) {
                const unsigned* p = &Eb[(warp_m + mm * 16 + gid) * LDK + ks + tig];
                af[mm][0] = p[0];
                af[mm][1] = p[8 * LDK];
                af[mm][2] = p[4];
                af[mm][3] = p[8 * LDK + 4];
            }
            #pragma unroll
            for (int nn = 0; nn < 2; nn++) {
                const unsigned* p = &Vb[(ks + tig) * LDN + warp_n + nn * 8 + gid];
                bf[nn][0] = p[0];
                bf[nn][1] = p[4 * LDN];
            }
            #pragma unroll
            for (int mm = 0; mm < 2; mm++)
                #pragma unroll
                for (int nn = 0; nn < 2; nn++)
                    mma_tf32(acc[mm][nn], af[mm], bf[nn]);
        }
    }

    #pragma unroll
    for (int mm = 0; mm < 2; mm++) {
        int a  = warp_m + mm * 16 + gid;
        int r0 = rb + a;
        float sa = sinv[a];
        float sb = sinv[a + 8];
        #pragma unroll
        for (int nn = 0; nn < 2; nn++) {
            int c = nb + warp_n + nn * 8 + 2 * tig;
            *(float2*)&C[(size_t)r0 * DIM_V + c] =
                make_float2(acc[mm][nn][0] * sa, acc[mm][nn][1] * sa);
            *(float2*)&C[(size_t)(r0 + 8) * DIM_V + c] =
                make_float2(acc[mm][nn][2] * sb, acc[mm][nn][3] * sb);
        }
    }
}

// ---------------------------------------------------------------------------
// Launch: 4 parallel chains (fork-join, no cross-chain edges), with
// Programmatic Dependent Launch on the in-chain edges:
//   proj --PDL--> score --PDL--> av
// so score/av CTAs launch early, squat, and prefetch under their producers.
// ---------------------------------------------------------------------------
extern "C" void kernel_launch(void* const* d_in, const int* in_sizes, int n_in,
                              void* d_out, int out_size)
{
    const float* query  = (const float*)d_in[0];
    const float* keys   = (const float*)d_in[1];
    const float* values = (const float*)d_in[2];
    const float* Wx     = (const float*)d_in[3];
    const float* Wh     = (const float*)d_in[4];
    const float* bh     = (const float*)d_in[5];
    const float* w      = (const float*)d_in[6];
    float* out = (float*)d_out;

    cudaStream_t st[BB];
    cudaEvent_t  evFork, evJoin[BB];
    for (int b = 0; b < BB; b++)
        cudaStreamCreateWithFlags(&st[b], cudaStreamNonBlocking);
    cudaEventCreateWithFlags(&evFork, cudaEventDisableTiming);
    for (int b = 0; b < BB; b++)
        cudaEventCreateWithFlags(&evJoin[b], cudaEventDisableTiming);

    cudaEventRecord(evFork, 0);

    cudaLaunchAttribute pdlAttr;
    pdlAttr.id = cudaLaunchAttributeProgrammaticStreamSerialization;
    pdlAttr.val.programmaticStreamSerializationAllowed = 1;

    for (int b = 0; b < BB; b++) {
        cudaStreamWaitEvent(st[b], evFork, 0);

        proj_tc<<<dim3(DIM_M / 64, LEN / 64, 3), 256, 0, st[b]>>>(
            keys, query, Wx, Wh, bh, values, b);

        {   // score with PDL (dependent of proj)
            cudaLaunchConfig_t cfg = {};
            cfg.gridDim = dim3(LEN / 32, LEN1 / 32, 1);
            cfg.blockDim = dim3(256, 1, 1);
            cfg.dynamicSmemBytes = 0;
            cfg.stream = st[b];
            cfg.attrs = &pdlAttr;
            cfg.numAttrs = 1;
            cudaLaunchKernelEx(&cfg, score_kernel, w, b);
        }

        {   // av with PDL (dependent of score)
            cudaLaunchConfig_t cfg = {};
            cfg.gridDim = dim3(DIM_V / 64, LEN1 / 64, 1);
            cfg.blockDim = dim3(256, 1, 1);
            cfg.dynamicSmemBytes = 0;
            cfg.stream = st[b];
            cfg.attrs = &pdlAttr;
            cfg.numAttrs = 1;
            cudaLaunchKernelEx(&cfg, av_tc, out, b);
        }

        cudaEventRecord(evJoin[b], st[b]);
    }

    for (int b = 0; b < BB; b++)
        cudaStreamWaitEvent((cudaStream_t)0, evJoin[b], 0);

    cudaEventDestroy(evFork);
    for (int b = 0; b < BB; b++) {
        cudaEventDestroy(evJoin[b]);
        cudaStreamDestroy(st[b]);
    }
}

// round 14
// speedup vs baseline: 1.0961x; 1.0961x over previous
#include <cuda_runtime.h>
#include <cuda_bf16.h>
#include <cstdint>

#define BB 4
#define LEN 512
#define LEN1 512
#define DIM_IN 512
#define DIM_H 512
#define DIM_M 256
#define DIM_V 512

#define LDK 20   // smem k-stride (16 k + 4 pad) words
#define LDN 72   // smem n-stride (64 n + 8 pad) words
#define LDS_M 257  // score smem row stride (odd -> conflict-free LDS)

#define L2E 1.4426950408889634f

// Scratch
__device__ __align__(16) float    g_kx[BB * LEN * DIM_M];   // [b][l][m]
__device__ __align__(16) float    g_qh[BB * LEN1 * DIM_M];  // [b][q][m]
__device__ __align__(16) float    g_sc[BB * LEN1 * LEN];    // [b][q][l]: exp(s) as tf32 bits
__device__ __align__(16) unsigned g_vt[BB * LEN * DIM_V];   // values as tf32 bits
__device__ __align__(16) float    g_part[BB * LEN1 * 16];   // per (row, l-tile): S_tile

// score dynamic smem: kxs[32][257] + qhs[32][257] + w[256]
#define SCORE_SMEM ((2 * 32 * LDS_M + DIM_M) * 4)

__device__ __forceinline__ float tanh_fast(float x) {
    float y;
    asm("tanh.approx.f32 %0, %1;" : "=f"(y) : "f"(x));
    return y;
}
__device__ __forceinline__ unsigned f2tf(float x) {
    unsigned u;
    asm("cvt.rna.tf32.f32 %0, %1;" : "=r"(u) : "f"(x));
    return u;
}
__device__ __forceinline__ void mma_tf32(float* d, const unsigned* a, const unsigned* b) {
    asm volatile(
        "mma.sync.aligned.m16n8k8.row.col.f32.tf32.tf32.f32 "
        "{%0,%1,%2,%3}, {%4,%5,%6,%7}, {%8,%9}, {%0,%1,%2,%3};"
        : "+f"(d[0]), "+f"(d[1]), "+f"(d[2]), "+f"(d[3])
        : "r"(a[0]), "r"(a[1]), "r"(a[2]), "r"(a[3]), "r"(b[0]), "r"(b[1]));
}
__device__ __forceinline__ void cp16(uint32_t smem_dst, const void* gmem_src) {
    asm volatile("cp.async.cg.shared.global [%0], [%1], 16;"
                 :: "r"(smem_dst), "l"(gmem_src));
}
#define CP_COMMIT() asm volatile("cp.async.commit_group;")
#define CP_WAIT2()  asm volatile("cp.async.wait_group 2;" ::: "memory")

// ---------------------------------------------------------------------------
// proj (NT, tf32 mma, 4-stage cp.async), per batch b. Block 64x64, 8 warps.
// z=0: keys[b]@Wx -> g_kx[b] ; z=1: query[b]@Wh + bh -> g_qh[b] ;
// z=2: rider blocks convert values[b] (fp32) -> g_vt[b] (tf32 bits).
// ---------------------------------------------------------------------------
__global__ __launch_bounds__(256) void proj_tc(
    const float* __restrict__ keys, const float* __restrict__ query,
    const float* __restrict__ Wx, const float* __restrict__ Wh,
    const float* __restrict__ bh, const float* __restrict__ values, int b)
{
    int tid = threadIdx.x;

    if (blockIdx.z == 2) {
        size_t base = (size_t)b * LEN * DIM_V / 4;
        const float4* src = (const float4*)values + base;
        uint4* dst = (uint4*)g_vt + base;
        int blk = blockIdx.y * 4 + blockIdx.x;        // 0..31
        int t   = blk * 256 + tid;                    // 0..8191
        #pragma unroll
        for (int i = 0; i < 8; i++) {
            int idx = t + i * 8192;
            float4 v = src[idx];
            uint4 u;
            u.x = f2tf(v.x); u.y = f2tf(v.y); u.z = f2tf(v.z); u.w = f2tf(v.w);
            dst[idx] = u;
        }
        return;
    }

    const float* A; const float* W; float* C; const float* bias;
    if (blockIdx.z == 0) {
        A = keys  + (size_t)b * LEN * DIM_IN;  W = Wx;
        C = g_kx  + (size_t)b * LEN * DIM_M;   bias = nullptr;
    } else {
        A = query + (size_t)b * LEN1 * DIM_H;  W = Wh;
        C = g_qh  + (size_t)b * LEN1 * DIM_M;  bias = bh;
    }

    __shared__ __align__(16) float As[4][64 * LDK];
    __shared__ __align__(16) float Ws[4][64 * LDK];

    int lane = tid & 31;
    int wid  = tid >> 5;
    int warp_m = (wid & 1) * 32;
    int warp_n = (wid >> 1) * 16;
    int gid = lane >> 2;
    int tig = lane & 3;

    int rb = blockIdx.y * 64;
    int nb = blockIdx.x * 64;

    int crow = tid >> 2;
    int cku  = (tid & 3) * 4;
    const float* Agp = A + (size_t)(rb + crow) * 512 + cku;
    const float* Wgp = W + (size_t)(nb + crow) * 512 + cku;
    uint32_t sA = (uint32_t)__cvta_generic_to_shared(&As[0][0]) + (crow * LDK + cku) * 4;
    uint32_t sW = (uint32_t)__cvta_generic_to_shared(&Ws[0][0]) + (crow * LDK + cku) * 4;
    const uint32_t stageB = 64 * LDK * 4;

    float acc[2][2][4] = {};

    #pragma unroll
    for (int s = 0; s < 3; s++) {
        cp16(sA + s * stageB, Agp + s * 16);
        cp16(sW + s * stageB, Wgp + s * 16);
        CP_COMMIT();
    }

    for (int i = 0; i < 32; i++) {
        CP_WAIT2();
        __syncthreads();
        int ls = i + 3;
        if (ls < 32) {
            uint32_t off = (uint32_t)(ls & 3) * stageB;
            cp16(sA + off, Agp + ls * 16);
            cp16(sW + off, Wgp + ls * 16);
        }
        CP_COMMIT();

        const float* Ab = &As[i & 3][0];
        const float* Wb = &Ws[i & 3][0];
        #pragma unroll
        for (int ks = 0; ks < 16; ks += 8) {
            unsigned af[2][4], bf[2][2];
            #pragma unroll
            for (int mm = 0; mm < 2; mm++) {
                const float* p = &Ab[(warp_m + mm * 16 + gid) * LDK + ks + tig];
                af[mm][0] = f2tf(p[0]);
                af[mm][1] = f2tf(p[8 * LDK]);
                af[mm][2] = f2tf(p[4]);
                af[mm][3] = f2tf(p[8 * LDK + 4]);
            }
            #pragma unroll
            for (int nn = 0; nn < 2; nn++) {
                const float* p = &Wb[(warp_n + nn * 8 + gid) * LDK + ks + tig];
                bf[nn][0] = f2tf(p[0]);
                bf[nn][1] = f2tf(p[4]);
            }
            #pragma unroll
            for (int mm = 0; mm < 2; mm++)
                #pragma unroll
                for (int nn = 0; nn < 2; nn++)
                    mma_tf32(acc[mm][nn], af[mm], bf[nn]);
        }
    }

    #pragma unroll
    for (int mm = 0; mm < 2; mm++) {
        int r0 = rb + warp_m + mm * 16 + gid;
        #pragma unroll
        for (int nn = 0; nn < 2; nn++) {
            int c = nb + warp_n + nn * 8 + 2 * tig;
            float2 v0 = make_float2(acc[mm][nn][0], acc[mm][nn][1]);
            float2 v1 = make_float2(acc[mm][nn][2], acc[mm][nn][3]);
            if (bias) {
                float2 bb = *(const float2*)&bias[c];
                v0.x += bb.x; v0.y += bb.y;
                v1.x += bb.x; v1.y += bb.y;
            }
            *(float2*)&C[(size_t)r0 * DIM_M + c]       = v0;
            *(float2*)&C[(size_t)(r0 + 8) * DIM_M + c] = v1;
        }
    }
}

// ---------------------------------------------------------------------------
// Scores, per batch b. SINGLE load phase, ONE barrier, then an uninterrupted
// 256-step MUFU loop.
// smem layout [row][m] with row stride 257 (odd):
//   compute LDS kxs[2tx][m]: bank = (2tx*257+m)%32 = (2tx+m)%32 -> 16 distinct
//   even banks (other half-warp broadcasts); row 2tx+1 hits the odd banks.
//   qa / w_s are warp broadcasts. Loads are float4 LDG, fully coalesced.
// Stores e = exp2(s*L2E) as tf32 bits + per-(row, 32-l-tile) sums in g_part.
// ---------------------------------------------------------------------------
__global__ __launch_bounds__(256) void score_kernel(const float* __restrict__ w, int b)
{
    extern __shared__ float sm[];
    float* kxs = sm;                       // [32][257]
    float* qhs = sm + 32 * LDS_M;          // [32][257]
    float* w_s = sm + 2 * 32 * LDS_M;      // [256]

    int tid = threadIdx.x;
    int tx = tid & 15, ty = tid >> 4;
    int lb = blockIdx.x * 32;
    int qb = blockIdx.y * 32;

    w_s[tid] = w[tid];

    const float4* kxp = (const float4*)(g_kx + (size_t)(b * LEN  + lb) * DIM_M);
    const float4* qhp = (const float4*)(g_qh + (size_t)(b * LEN1 + qb) * DIM_M);

    // Load both 32x256 slabs. 2048 float4 per slab; 8 per thread.
    #pragma unroll
    for (int i = 0; i < 8; i++) {
        int idx = i * 256 + tid;          // 0..2047
        int row = idx >> 6;               // /64
        int m   = (idx & 63) << 2;        // *4
        float4 kv = kxp[idx];
        float4 qv = qhp[idx];
        float* kd = &kxs[row * LDS_M + m];
        float* qd = &qhs[row * LDS_M + m];
        kd[0] = kv.x; kd[1] = kv.y; kd[2] = kv.z; kd[3] = kv.w;
        qd[0] = qv.x; qd[1] = qv.y; qd[2] = qv.z; qd[3] = qv.w;
    }
    __syncthreads();

    const float* k0p = &kxs[(tx * 2) * LDS_M];
    const float* k1p = &kxs[(tx * 2 + 1) * LDS_M];
    const float* q0p = &qhs[(ty * 2) * LDS_M];
    const float* q1p = &qhs[(ty * 2 + 1) * LDS_M];

    float acc00 = 0.f, acc01 = 0.f, acc10 = 0.f, acc11 = 0.f;

    #pragma unroll 8
    for (int m = 0; m < 256; m++) {
        float wm = w_s[m];
        float k0 = k0p[m], k1 = k1p[m];
        float q0 = q0p[m], q1 = q1p[m];
        acc00 += wm * tanh_fast(q0 + k0);
        acc01 += wm * tanh_fast(q0 + k1);
        acc10 += wm * tanh_fast(q1 + k0);
        acc11 += wm * tanh_fast(q1 + k1);
    }

    float e00 = exp2f(acc00 * L2E);
    float e01 = exp2f(acc01 * L2E);
    float e10 = exp2f(acc10 * L2E);
    float e11 = exp2f(acc11 * L2E);

    float S0 = e00 + e01;
    float S1 = e10 + e11;
    #pragma unroll
    for (int s = 1; s < 16; s <<= 1) {
        S0 += __shfl_xor_sync(0xFFFFFFFFu, S0, s);
        S1 += __shfl_xor_sync(0xFFFFFFFFu, S1, s);
    }

    float* o = g_sc + (size_t)(b * LEN1 + qb + ty * 2) * LEN + lb + tx * 2;
    o[0]       = __uint_as_float(f2tf(e00));
    o[1]       = __uint_as_float(f2tf(e01));
    o[LEN]     = __uint_as_float(f2tf(e10));
    o[LEN + 1] = __uint_as_float(f2tf(e11));

    if (tx == 0) {
        int q0i = qb + ty * 2;
        float* pp = g_part + (size_t)(b * LEN1 + q0i) * 16 + blockIdx.x;
        pp[0]  = S0;
        pp[16] = S1;
    }
}

// ---------------------------------------------------------------------------
// av (NN, tf32 mma, 4-stage cp.async), per batch b. Block 64x64, 8 warps.
// Pure LDS+mma mainloop (E and V are tf32 bits). 1/S_row in the epilogue.
// ---------------------------------------------------------------------------
__global__ __launch_bounds__(256) void av_tc(float* __restrict__ out, int b)
{
    const unsigned* E = (const unsigned*)g_sc + (size_t)b * LEN1 * LEN;
    const unsigned* V = g_vt + (size_t)b * LEN * DIM_V;
    float*          C = out  + (size_t)b * LEN1 * DIM_V;

    __shared__ __align__(16) unsigned Es[4][64 * LDK];
    __shared__ __align__(16) unsigned Vs[4][16 * LDN];
    __shared__ float sinv[64];

    int tid  = threadIdx.x;
    int lane = tid & 31;
    int wid  = tid >> 5;
    int warp_m = (wid & 1) * 32;
    int warp_n = (wid >> 1) * 16;
    int gid = lane >> 2;
    int tig = lane & 3;

    int rb = blockIdx.y * 64;
    int nb = blockIdx.x * 64;

    int erow = tid >> 2;
    int eku  = (tid & 3) * 4;
    int vrow = tid >> 4;
    int vu   = (tid & 15) * 4;
    const unsigned* Egp = E + (size_t)(rb + erow) * LEN + eku;
    const unsigned* Vgp = V + (size_t)vrow * DIM_V + nb + vu;
    uint32_t sE = (uint32_t)__cvta_generic_to_shared(&Es[0][0]) + (erow * LDK + eku) * 4;
    uint32_t sV = (uint32_t)__cvta_generic_to_shared(&Vs[0][0]) + (vrow * LDN + vu) * 4;
    const uint32_t stageE = 64 * LDK * 4;
    const uint32_t stageV = 16 * LDN * 4;

    float acc[2][2][4] = {};

    #pragma unroll
    for (int s = 0; s < 3; s++) {
        cp16(sE + s * stageE, Egp + s * 16);
        cp16(sV + s * stageV, Vgp + (size_t)s * 16 * DIM_V);
        CP_COMMIT();
    }

    // Prologue: per-row inverse sums (threads 0..63, one row each).
    if (tid < 64) {
        const float4* pp = (const float4*)&g_part[(size_t)(b * LEN1 + rb + tid) * 16];
        float4 p0 = pp[0], p1 = pp[1], p2 = pp[2], p3 = pp[3];
        float S = ((p0.x + p0.y) + (p0.z + p0.w))
                + ((p1.x + p1.y) + (p1.z + p1.w))
                + ((p2.x + p2.y) + (p2.z + p2.w))
                + ((p3.x + p3.y) + (p3.z + p3.w));
        sinv[tid] = 1.0f / S;
    }
    __syncthreads();

    for (int i = 0; i < 32; i++) {
        CP_WAIT2();
        __syncthreads();
        int ls = i + 3;
        if (ls < 32) {
            uint32_t offE = (uint32_t)(ls & 3) * stageE;
            uint32_t offV = (uint32_t)(ls & 3) * stageV;
            cp16(sE + offE, Egp + ls * 16);
            cp16(sV + offV, Vgp + (size_t)ls * 16 * DIM_V);
        }
        CP_COMMIT();

        const unsigned* Eb = &Es[i & 3][0];
        const unsigned* Vb = &Vs[i & 3][0];
        #pragma unroll
        for (int ks = 0; ks < 16; ks += 8) {
            unsigned af[2][4], bf[2][2];
            #pragma unroll
            for (int mm = 0; mm < 2; mm++) {
                const unsigned* p = &Eb[(warp_m + mm * 16 + gid) * LDK + ks + tig];
                af[mm][0] = p[0];
                af[mm][1] = p[8 * LDK];
                af[mm][2] = p[4];
                af[mm][3] = p[8 * LDK + 4];
            }
            #pragma unroll
            for (int nn = 0; nn < 2; nn++) {
                const unsigned* p = &Vb[(ks + tig) * LDN + warp_n + nn * 8 + gid];
                bf[nn][0] = p[0];
                bf[nn][1] = p[4 * LDN];
            }
            #pragma unroll
            for (int mm = 0; mm < 2; mm++)
                #pragma unroll
                for (int nn = 0; nn < 2; nn++)
                    mma_tf32(acc[mm][nn], af[mm], bf[nn]);
        }
    }

    #pragma unroll
    for (int mm = 0; mm < 2; mm++) {
        int a  = warp_m + mm * 16 + gid;
        int r0 = rb + a;
        float sa = sinv[a];
        float sb = sinv[a + 8];
        #pragma unroll
        for (int nn = 0; nn < 2; nn++) {
            int c = nb + warp_n + nn * 8 + 2 * tig;
            *(float2*)&C[(size_t)r0 * DIM_V + c] =
                make_float2(acc[mm][nn][0] * sa, acc[mm][nn][1] * sa);
            *(float2*)&C[(size_t)(r0 + 8) * DIM_V + c] =
                make_float2(acc[mm][nn][2] * sb, acc[mm][nn][3] * sb);
        }
    }
}

// ---------------------------------------------------------------------------
// Launch: 4 parallel chains, plain fork-join (best-measured topology).
// Chain b: proj(+vt rider) -> score -> av(epilogue normalize).
// ---------------------------------------------------------------------------
extern "C" void kernel_launch(void* const* d_in, const int* in_sizes, int n_in,
                              void* d_out, int out_size)
{
    const float* query  = (const float*)d_in[0];
    const float* keys   = (const float*)d_in[1];
    const float* values = (const float*)d_in[2];
    const float* Wx     = (const float*)d_in[3];
    const float* Wh     = (const float*)d_in[4];
    const float* bh     = (const float*)d_in[5];
    const float* w      = (const float*)d_in[6];
    float* out = (float*)d_out;

    cudaFuncSetAttribute(score_kernel,
                         cudaFuncAttributeMaxDynamicSharedMemorySize, SCORE_SMEM);

    cudaStream_t st[BB];
    cudaEvent_t  evFork, evJoin[BB];
    for (int b = 0; b < BB; b++)
        cudaStreamCreateWithFlags(&st[b], cudaStreamNonBlocking);
    cudaEventCreateWithFlags(&evFork, cudaEventDisableTiming);
    for (int b = 0; b < BB; b++)
        cudaEventCreateWithFlags(&evJoin[b], cudaEventDisableTiming);

    cudaEventRecord(evFork, 0);

    for (int b = 0; b < BB; b++) {
        cudaStreamWaitEvent(st[b], evFork, 0);
        proj_tc<<<dim3(DIM_M / 64, LEN / 64, 3), 256, 0, st[b]>>>(
            keys, query, Wx, Wh, bh, values, b);
        score_kernel<<<dim3(LEN / 32, LEN1 / 32), 256, SCORE_SMEM, st[b]>>>(w, b);
        av_tc<<<dim3(DIM_V / 64, LEN1 / 64), 256, 0, st[b]>>>(out, b);
        cudaEventRecord(evJoin[b], st[b]);
    }

    for (int b = 0; b < BB; b++)
        cudaStreamWaitEvent((cudaStream_t)0, evJoin[b], 0);

    cudaEventDestroy(evFork);
    for (int b = 0; b < BB; b++) {
        cudaEventDestroy(evJoin[b]);
        cudaStreamDestroy(st[b]);
    }
}